// round 2
// baseline (speedup 1.0000x reference)
#include <cuda_runtime.h>

#define NN 100000
#define EE 1600000
#define FEADIM 128
#define HH 64
#define GG 512
#define NLAYERS 4
#define BN_EPS 1e-5f

// ---------------- scratch (static device globals; no allocation) ----------------
__device__ float g_tA[(size_t)NN * HH];        // raw GEMM output (pre-BN)
__device__ float g_tB[(size_t)NN * HH];        // raw GEMM output (pre-BN)
__device__ float g_h[(size_t)NN * HH];         // activated node features
__device__ float g_z[(size_t)NN * HH];         // h + aggregated neighbors
__device__ float g_stats[10 * 128];            // per-stage [sum(64), sumsq(64)]
__device__ float g_ab[10 * 128];               // per-stage [a(64), c(64)] BN affine
__device__ float g_pooled[(NLAYERS + 1) * GG * HH];
__device__ int   g_cnt[GG];

// vectorized fp32 reduction (sm_90+)
__device__ __forceinline__ void red_add_v4(float* p, float4 v) {
    asm volatile("red.global.add.v4.f32 [%0], {%1,%2,%3,%4};"
                 :: "l"(p), "f"(v.x), "f"(v.y), "f"(v.z), "f"(v.w) : "memory");
}

// ---------------- kernels ----------------

__global__ void zero_kernel() {
    int i = blockIdx.x * blockDim.x + threadIdx.x;
    if (i < 10 * 128) g_stats[i] = 0.f;
    if (i < (NLAYERS + 1) * GG * HH) g_pooled[i] = 0.f;
    if (i < GG) g_cnt[i] = 0;
}

__global__ void count_kernel(const int* __restrict__ batch) {
    int i = blockIdx.x * blockDim.x + threadIdx.x;
    if (i < NN) atomicAdd(&g_cnt[batch[i]], 1);
}

// Tiled GEMM: Y[N,64] = f(A)[N,K] @ W[K,64] + bias, where f is optional
// per-input-feature relu(a*x+c) (the folded BN+ReLU of the previous stage).
// Also accumulates per-column sum / sumsq of Y (valid rows only) into stats.
// Asel: 0 -> Aext (external x), 1 -> g_tA, 2 -> g_z
// Ysel: 0 -> g_tA, 1 -> g_tB
// tstage: -1 -> no input transform, else stage index into g_ab
__global__ __launch_bounds__(256) void gemm_bn_kernel(
    const float* __restrict__ Aext, int Asel, int K,
    const float* __restrict__ W, const float* __restrict__ bias,
    int tstage, int Ysel, int sstage)
{
    const float* A = (Asel == 0) ? Aext : (Asel == 1 ? g_tA : g_z);
    float* Y = (Ysel == 0) ? g_tA : g_tB;
    const float* trans = (tstage >= 0) ? (g_ab + tstage * 128) : nullptr;
    float* stats = g_stats + sstage * 128;

    __shared__ float As[64][68];
    __shared__ float Bs[64][68];
    int tid = threadIdx.x;
    int tx = tid & 15, ty = tid >> 4;
    int tx4 = tx * 4, ty4 = ty * 4;
    int row0 = blockIdx.x * 64;

    float acc[16];
#pragma unroll
    for (int i = 0; i < 16; i++) acc[i] = 0.f;

    for (int k0 = 0; k0 < K; k0 += 64) {
#pragma unroll
        for (int i = 0; i < 4; i++) {
            int li = tid + i * 256;          // 0..1023 over 64 rows x 16 float4
            int r = li >> 4, c4 = li & 15;
            int grow = row0 + r;
            float4 v = make_float4(0.f, 0.f, 0.f, 0.f);
            if (grow < NN) v = *(const float4*)(A + (size_t)grow * K + k0 + c4 * 4);
            if (trans) {
                int kb = k0 + c4 * 4;
                v.x = fmaxf(0.f, trans[kb + 0] * v.x + trans[64 + kb + 0]);
                v.y = fmaxf(0.f, trans[kb + 1] * v.y + trans[64 + kb + 1]);
                v.z = fmaxf(0.f, trans[kb + 2] * v.z + trans[64 + kb + 2]);
                v.w = fmaxf(0.f, trans[kb + 3] * v.w + trans[64 + kb + 3]);
            }
            *(float4*)(&As[r][c4 * 4]) = v;
            float4 w = *(const float4*)(W + (size_t)(k0 + r) * 64 + c4 * 4);
            *(float4*)(&Bs[r][c4 * 4]) = w;
        }
        __syncthreads();
#pragma unroll 8
        for (int kk = 0; kk < 64; kk++) {
            float4 b = *(const float4*)(&Bs[kk][tx4]);
            float a0 = As[ty4 + 0][kk];
            float a1 = As[ty4 + 1][kk];
            float a2 = As[ty4 + 2][kk];
            float a3 = As[ty4 + 3][kk];
            acc[0]  += a0 * b.x; acc[1]  += a0 * b.y; acc[2]  += a0 * b.z; acc[3]  += a0 * b.w;
            acc[4]  += a1 * b.x; acc[5]  += a1 * b.y; acc[6]  += a1 * b.z; acc[7]  += a1 * b.w;
            acc[8]  += a2 * b.x; acc[9]  += a2 * b.y; acc[10] += a2 * b.z; acc[11] += a2 * b.w;
            acc[12] += a3 * b.x; acc[13] += a3 * b.y; acc[14] += a3 * b.z; acc[15] += a3 * b.w;
        }
        __syncthreads();
    }

    float b0 = bias[tx4], b1 = bias[tx4 + 1], b2 = bias[tx4 + 2], b3 = bias[tx4 + 3];
    float s[4] = {0, 0, 0, 0}, q[4] = {0, 0, 0, 0};
#pragma unroll
    for (int i = 0; i < 4; i++) {
        int grow = row0 + ty4 + i;
        if (grow < NN) {
            float4 y;
            y.x = acc[i * 4 + 0] + b0;
            y.y = acc[i * 4 + 1] + b1;
            y.z = acc[i * 4 + 2] + b2;
            y.w = acc[i * 4 + 3] + b3;
            *(float4*)(Y + (size_t)grow * 64 + tx4) = y;
            s[0] += y.x; s[1] += y.y; s[2] += y.z; s[3] += y.w;
            q[0] += y.x * y.x; q[1] += y.y * y.y; q[2] += y.z * y.z; q[3] += y.w * y.w;
        }
    }
    // block reduce (reuse As) then 128 global REDs per block
    __syncthreads();
    float* red = &As[0][0];
#pragma unroll
    for (int j = 0; j < 4; j++) {
        red[ty * 128 + tx4 + j]      = s[j];
        red[ty * 128 + 64 + tx4 + j] = q[j];
    }
    __syncthreads();
    if (tid < 128) {
        float tot = 0.f;
#pragma unroll
        for (int t = 0; t < 16; t++) tot += red[t * 128 + tid];
        atomicAdd(&stats[tid], tot);
    }
}

__global__ void bn_finalize(int sstage,
                            const float* __restrict__ gamma,
                            const float* __restrict__ beta)
{
    const float* stats = g_stats + sstage * 128;
    float* ab = g_ab + sstage * 128;
    int j = threadIdx.x;  // 64 threads
    float m = stats[j] * (1.f / NN);
    float v = stats[64 + j] * (1.f / NN) - m * m;
    float a = gamma[j] * rsqrtf(v + BN_EPS);
    ab[j] = a;
    ab[64 + j] = beta[j] - a * m;
}

// h = relu(a*t + c); z = h (scatter base); pooled[level][batch] += h
__global__ void epilogue_kernel(int sstage, int level,
                                const int* __restrict__ batch)
{
    const float* T = g_tB;
    const float* ab = g_ab + sstage * 128;
    float* pooled_level = g_pooled + (size_t)level * GG * HH;
    int tid = blockIdx.x * blockDim.x + threadIdx.x;
    int r = tid >> 4, qq = tid & 15;
    if (r >= NN) return;
    int c = qq * 4;
    float4 v = *(const float4*)(T + (size_t)r * 64 + c);
    float4 u;
    u.x = fmaxf(0.f, ab[c + 0] * v.x + ab[64 + c + 0]);
    u.y = fmaxf(0.f, ab[c + 1] * v.y + ab[64 + c + 1]);
    u.z = fmaxf(0.f, ab[c + 2] * v.z + ab[64 + c + 2]);
    u.w = fmaxf(0.f, ab[c + 3] * v.w + ab[64 + c + 3]);
    *(float4*)(g_h + (size_t)r * 64 + c) = u;
    *(float4*)(g_z + (size_t)r * 64 + c) = u;
    int g = batch[r];
    red_add_v4(pooled_level + (size_t)g * 64 + c, u);
}

// z[dst] += h[src] over all edges, 16 threads per edge, v4 atomics
__global__ void scatter_kernel(const int* __restrict__ src, const int* __restrict__ dst) {
    int tid = blockIdx.x * blockDim.x + threadIdx.x;
    int e = tid >> 4, qq = tid & 15;
    if (e >= EE) return;
    int s = src[e], d = dst[e];
    float4 v = *(const float4*)(g_h + (size_t)s * 64 + qq * 4);
    red_add_v4(g_z + (size_t)d * 64 + qq * 4, v);
}

// out[g,t] = sum_l pooled[l][g]·linW[l][:,t] + cnt[g]*linb[0,t] + sum_{l>=1} linb[l,t]
__global__ void final_kernel(const float* __restrict__ linW,
                             const float* __restrict__ linb,
                             float* __restrict__ out)
{
    __shared__ float ps[(NLAYERS + 1) * 64];
    int g = blockIdx.x, t = threadIdx.x;  // 512 blocks x 64 threads
    for (int i = t; i < (NLAYERS + 1) * 64; i += 64) {
        int l = i >> 6, j = i & 63;
        ps[i] = g_pooled[(size_t)l * GG * 64 + (size_t)g * 64 + j];
    }
    __syncthreads();
    float acc = (float)g_cnt[g] * linb[t];
#pragma unroll
    for (int l = 1; l < NLAYERS + 1; l++) acc += linb[l * 64 + t];
    for (int l = 0; l < NLAYERS + 1; l++) {
        const float* wl = linW + (size_t)l * 64 * 64;
#pragma unroll 8
        for (int j = 0; j < 64; j++)
            acc += ps[l * 64 + j] * wl[j * 64 + t];
    }
    out[(size_t)g * 64 + t] = acc;
}

// ---------------- launch ----------------

extern "C" void kernel_launch(void* const* d_in, const int* in_sizes, int n_in,
                              void* d_out, int out_size)
{
    const float* x     = (const float*)d_in[0];
    const int*   edge  = (const int*)d_in[1];   // [2,E]: src then dst
    const int*   batch = (const int*)d_in[2];
    const float* fW1 = (const float*)d_in[3];
    const float* fb1 = (const float*)d_in[4];
    const float* fg1 = (const float*)d_in[5];
    const float* fbt1= (const float*)d_in[6];
    const float* fW2 = (const float*)d_in[7];
    const float* fb2 = (const float*)d_in[8];
    const float* fg2 = (const float*)d_in[9];
    const float* fbt2= (const float*)d_in[10];
    const float* cW1 = (const float*)d_in[11];
    const float* cb1 = (const float*)d_in[12];
    const float* cg1 = (const float*)d_in[13];
    const float* cbt1= (const float*)d_in[14];
    const float* cW2 = (const float*)d_in[15];
    const float* cb2 = (const float*)d_in[16];
    const float* cg2 = (const float*)d_in[17];
    const float* cbt2= (const float*)d_in[18];
    const float* linW= (const float*)d_in[19];
    const float* linb= (const float*)d_in[20];

    const int gemm_blocks = (NN + 63) / 64;   // 1563

    zero_kernel<<<640, 256>>>();
    count_kernel<<<(NN + 255) / 256, 256>>>(batch);

    // first_h: Linear(128,64)+BN+ReLU -> Linear(64,64)+BN+ReLU
    gemm_bn_kernel<<<gemm_blocks, 256>>>(x, 0, FEADIM, fW1, fb1, -1, 0, 0);
    bn_finalize<<<1, 64>>>(0, fg1, fbt1);
    gemm_bn_kernel<<<gemm_blocks, 256>>>(nullptr, 1, HH, fW2, fb2, 0, 1, 1);
    bn_finalize<<<1, 64>>>(1, fg2, fbt2);
    epilogue_kernel<<<(NN * 16 + 255) / 256, 256>>>(1, 0, batch);

    for (int l = 0; l < NLAYERS; l++) {
        int sA = 2 + 2 * l, sB = 3 + 2 * l;
        scatter_kernel<<<(EE * 16) / 256, 256>>>(edge, edge + EE);
        gemm_bn_kernel<<<gemm_blocks, 256>>>(nullptr, 2, HH,
                                             cW1 + (size_t)l * HH * HH, cb1 + l * HH,
                                             -1, 0, sA);
        bn_finalize<<<1, 64>>>(sA, cg1 + l * HH, cbt1 + l * HH);
        gemm_bn_kernel<<<gemm_blocks, 256>>>(nullptr, 1, HH,
                                             cW2 + (size_t)l * HH * HH, cb2 + l * HH,
                                             sA, 1, sB);
        bn_finalize<<<1, 64>>>(sB, cg2 + l * HH, cbt2 + l * HH);
        epilogue_kernel<<<(NN * 16 + 255) / 256, 256>>>(sB, l + 1, batch);
    }

    final_kernel<<<GG, 64>>>(linW, linb, (float*)d_out);
}

// round 4
// speedup vs baseline: 1.2574x; 1.2574x over previous
#include <cuda_runtime.h>

#define NN 100000
#define EE 1600000
#define FEADIM 128
#define HH 64
#define GG 512
#define NLAYERS 4
#define BN_EPS 1e-5f
#define SCAN_NBLK 98   // ceil((NN+1)/1024)

// ---------------- scratch (static device globals; no allocation) ----------------
__device__ float g_tA[(size_t)NN * HH];
__device__ float g_tB[(size_t)NN * HH];
__device__ float g_h[(size_t)NN * HH];
__device__ float g_z[(size_t)NN * HH];
__device__ float g_stats[10 * 128];            // per-stage [sum(64), sumsq(64)]
__device__ float g_ab[10 * 128];               // per-stage [a(64), c(64)] folded BN affine
__device__ float g_pooled[(NLAYERS + 1) * GG * HH];
__device__ int   g_cnt[GG];
__device__ int   g_deg[NN];
__device__ int   g_cur[NN];
__device__ int   g_off[NN + 1];
__device__ int   g_bsum[SCAN_NBLK];
__device__ int   g_bsum2[SCAN_NBLK];
__device__ int   g_csr[EE];
__device__ int   g_done[16];

__device__ __forceinline__ void red_add_v4(float* p, float4 v) {
    asm volatile("red.global.add.v4.f32 [%0], {%1,%2,%3,%4};"
                 :: "l"(p), "f"(v.x), "f"(v.y), "f"(v.z), "f"(v.w) : "memory");
}

// ---------------- setup kernels ----------------

__global__ void zero_kernel() {
    const int TOT = (NLAYERS + 1) * GG * HH;   // 163840, largest
    for (int i = blockIdx.x * blockDim.x + threadIdx.x; i < TOT;
         i += gridDim.x * blockDim.x) {
        g_pooled[i] = 0.f;
        if (i < NN) { g_deg[i] = 0; g_cur[i] = 0; }
        if (i < 10 * 128) g_stats[i] = 0.f;
        if (i < GG) g_cnt[i] = 0;
        if (i < 16) g_done[i] = 0;
    }
}

// degree histogram (dst) + per-graph node counts
__global__ void count_kernel(const int* __restrict__ edge, const int* __restrict__ batch) {
    int i = blockIdx.x * blockDim.x + threadIdx.x;
    if (i < EE) atomicAdd(&g_deg[edge[EE + i]], 1);
    if (i < NN) atomicAdd(&g_cnt[batch[i]], 1);
}

// exclusive scan of g_deg into g_off (3-phase)
__global__ void scan_block_kernel() {
    __shared__ int s[1024];
    int tid = threadIdx.x;
    int i = blockIdx.x * 1024 + tid;
    int v = (i < NN) ? g_deg[i] : 0;
    s[tid] = v;
    __syncthreads();
    for (int off = 1; off < 1024; off <<= 1) {
        int t = (tid >= off) ? s[tid - off] : 0;
        __syncthreads();
        s[tid] += t;
        __syncthreads();
    }
    if (i <= NN) g_off[i] = s[tid] - v;
    if (tid == 1023) g_bsum[blockIdx.x] = s[1023];
}

__global__ void scan_top_kernel() {
    __shared__ int s[128];
    int tid = threadIdx.x;
    int v = (tid < SCAN_NBLK) ? g_bsum[tid] : 0;
    s[tid] = v;
    __syncthreads();
    for (int off = 1; off < 128; off <<= 1) {
        int t = (tid >= off) ? s[tid - off] : 0;
        __syncthreads();
        s[tid] += t;
        __syncthreads();
    }
    if (tid < SCAN_NBLK) g_bsum2[tid] = s[tid] - v;
}

__global__ void scan_add_kernel() {
    int i = blockIdx.x * 1024 + threadIdx.x;
    if (i <= NN) g_off[i] += g_bsum2[i >> 10];
}

__global__ void fill_csr_kernel(const int* __restrict__ edge) {
    int e = blockIdx.x * blockDim.x + threadIdx.x;
    if (e >= EE) return;
    int d = edge[EE + e];
    int pos = g_off[d] + atomicAdd(&g_cur[d], 1);
    g_csr[pos] = edge[e];
}

// ---------------- GEMM with fused BN-stat reduction + BN finalize ----------------
// Y[N,64] = f(A)[N,K] @ W[K,64] + bias;  f = optional relu(a*x+c) from g_ab[tstage].
// Last block to finish computes the folded BN affine for this stage.
__global__ __launch_bounds__(256) void gemm_bn_kernel(
    const float* __restrict__ Aext, int Asel, int K,
    const float* __restrict__ W, const float* __restrict__ bias,
    int tstage, int Ysel, int sstage,
    const float* __restrict__ gamma, const float* __restrict__ beta)
{
    const float* A = (Asel == 0) ? Aext : (Asel == 1 ? g_tA : g_z);
    float* Y = (Ysel == 0) ? g_tA : g_tB;
    const float* trans = (tstage >= 0) ? (g_ab + tstage * 128) : nullptr;
    float* stats = g_stats + sstage * 128;

    __shared__ float As[64][68];
    __shared__ float Bs[64][68];
    __shared__ bool slast;
    int tid = threadIdx.x;
    int tx = tid & 15, ty = tid >> 4;
    int tx4 = tx * 4, ty4 = ty * 4;
    int row0 = blockIdx.x * 64;

    float acc[16];
#pragma unroll
    for (int i = 0; i < 16; i++) acc[i] = 0.f;

    for (int k0 = 0; k0 < K; k0 += 64) {
#pragma unroll
        for (int i = 0; i < 4; i++) {
            int li = tid + i * 256;
            int r = li >> 4, c4 = li & 15;
            int grow = row0 + r;
            float4 v = make_float4(0.f, 0.f, 0.f, 0.f);
            if (grow < NN) v = *(const float4*)(A + (size_t)grow * K + k0 + c4 * 4);
            if (trans) {
                int kb = k0 + c4 * 4;
                v.x = fmaxf(0.f, trans[kb + 0] * v.x + trans[64 + kb + 0]);
                v.y = fmaxf(0.f, trans[kb + 1] * v.y + trans[64 + kb + 1]);
                v.z = fmaxf(0.f, trans[kb + 2] * v.z + trans[64 + kb + 2]);
                v.w = fmaxf(0.f, trans[kb + 3] * v.w + trans[64 + kb + 3]);
            }
            *(float4*)(&As[r][c4 * 4]) = v;
            float4 w = *(const float4*)(W + (size_t)(k0 + r) * 64 + c4 * 4);
            *(float4*)(&Bs[r][c4 * 4]) = w;
        }
        __syncthreads();
#pragma unroll 8
        for (int kk = 0; kk < 64; kk++) {
            float4 b = *(const float4*)(&Bs[kk][tx4]);
            float a0 = As[ty4 + 0][kk];
            float a1 = As[ty4 + 1][kk];
            float a2 = As[ty4 + 2][kk];
            float a3 = As[ty4 + 3][kk];
            acc[0]  += a0 * b.x; acc[1]  += a0 * b.y; acc[2]  += a0 * b.z; acc[3]  += a0 * b.w;
            acc[4]  += a1 * b.x; acc[5]  += a1 * b.y; acc[6]  += a1 * b.z; acc[7]  += a1 * b.w;
            acc[8]  += a2 * b.x; acc[9]  += a2 * b.y; acc[10] += a2 * b.z; acc[11] += a2 * b.w;
            acc[12] += a3 * b.x; acc[13] += a3 * b.y; acc[14] += a3 * b.z; acc[15] += a3 * b.w;
        }
        __syncthreads();
    }

    float b0 = bias[tx4], b1 = bias[tx4 + 1], b2 = bias[tx4 + 2], b3 = bias[tx4 + 3];
    float s[4] = {0, 0, 0, 0}, q[4] = {0, 0, 0, 0};
#pragma unroll
    for (int i = 0; i < 4; i++) {
        int grow = row0 + ty4 + i;
        if (grow < NN) {
            float4 y;
            y.x = acc[i * 4 + 0] + b0;
            y.y = acc[i * 4 + 1] + b1;
            y.z = acc[i * 4 + 2] + b2;
            y.w = acc[i * 4 + 3] + b3;
            *(float4*)(Y + (size_t)grow * 64 + tx4) = y;
            s[0] += y.x; s[1] += y.y; s[2] += y.z; s[3] += y.w;
            q[0] += y.x * y.x; q[1] += y.y * y.y; q[2] += y.z * y.z; q[3] += y.w * y.w;
        }
    }
    __syncthreads();
    float* red = &As[0][0];
#pragma unroll
    for (int j = 0; j < 4; j++) {
        red[ty * 128 + tx4 + j]      = s[j];
        red[ty * 128 + 64 + tx4 + j] = q[j];
    }
    __syncthreads();
    if (tid < 128) {
        float tot = 0.f;
#pragma unroll
        for (int t = 0; t < 16; t++) tot += red[t * 128 + tid];
        atomicAdd(&stats[tid], tot);
        __threadfence();
    }
    __syncthreads();
    if (tid == 0) {
        int v = atomicAdd(&g_done[sstage], 1);
        slast = (v == (int)gridDim.x - 1);
    }
    __syncthreads();
    if (slast && tid < 64) {
        float s_ = __ldcg(&stats[tid]);
        float q_ = __ldcg(&stats[64 + tid]);
        float m = s_ * (1.f / NN);
        float var = q_ * (1.f / NN) - m * m;
        float a = gamma[tid] * rsqrtf(var + BN_EPS);
        g_ab[sstage * 128 + tid] = a;
        g_ab[sstage * 128 + 64 + tid] = beta[tid] - a * m;
    }
}

// ---------------- epilogue: h = relu(a*t+c); segmented pooling RED ----------------
// Every block-local run segment is emitted by its first row in the block:
// row rl emits iff (rl == 0 || batch changes at rl). This partitions all rows
// exactly once even when a graph's run spans multiple blocks.
__global__ __launch_bounds__(256) void epilogue_kernel(int sstage, int level,
                                                       const int* __restrict__ batch)
{
    __shared__ float4 su[16][17];
    __shared__ int sb[16];
    const float* T = g_tB;
    const float* ab = g_ab + sstage * 128;
    float* pooled_level = g_pooled + (size_t)level * GG * HH;
    int tid = threadIdx.x;
    int rl = tid >> 4, qq = tid & 15;
    int r = blockIdx.x * 16 + rl;
    int c = qq * 4;
    float4 u = make_float4(0.f, 0.f, 0.f, 0.f);
    int b = -1;
    if (r < NN) {
        float4 v = *(const float4*)(T + (size_t)r * 64 + c);
        u.x = fmaxf(0.f, ab[c + 0] * v.x + ab[64 + c + 0]);
        u.y = fmaxf(0.f, ab[c + 1] * v.y + ab[64 + c + 1]);
        u.z = fmaxf(0.f, ab[c + 2] * v.z + ab[64 + c + 2]);
        u.w = fmaxf(0.f, ab[c + 3] * v.w + ab[64 + c + 3]);
        *(float4*)(g_h + (size_t)r * 64 + c) = u;
        b = batch[r];
    }
    if (qq == 0) sb[rl] = b;
    su[rl][qq] = u;
    __syncthreads();
    if (r < NN) {
        bool head = (rl == 0) || (b != sb[rl - 1]);
        if (head) {
            float4 acc = u;
            for (int k = rl + 1; k < 16 && sb[k] == b; k++) {
                float4 w = su[k][qq];
                acc.x += w.x; acc.y += w.y; acc.z += w.z; acc.w += w.w;
            }
            red_add_v4(pooled_level + (size_t)b * 64 + c, acc);
        }
    }
}

// ---------------- CSR gather: z[i] = h[i] + sum_{j->i} h[j] ----------------
__global__ __launch_bounds__(256) void gather_kernel() {
    int gt = blockIdx.x * 256 + threadIdx.x;
    int node = gt >> 4;              // grid sized so node < NN always
    int lane16 = threadIdx.x & 15;
    int c = lane16 * 4;

    int off0 = g_off[node];
    int cnt = g_off[node + 1] - off0;

    float4 acc = *(const float4*)(g_h + (size_t)node * 64 + c);

    // warp-uniform loop bound (two nodes share a warp)
    int vmax = cnt;
#pragma unroll
    for (int sft = 16; sft > 0; sft >>= 1)
        vmax = max(vmax, __shfl_xor_sync(0xffffffffu, vmax, sft));

    for (int base = 0; base < vmax; base += 16) {
        int myidx = (base + lane16 < cnt) ? g_csr[off0 + base + lane16] : -1;
#pragma unroll
        for (int j = 0; j < 16; j++) {
            int idx = __shfl_sync(0xffffffffu, myidx, j, 16);
            if (idx >= 0) {
                float4 v = *(const float4*)(g_h + (size_t)idx * 64 + c);
                acc.x += v.x; acc.y += v.y; acc.z += v.z; acc.w += v.w;
            }
        }
    }
    *(float4*)(g_z + (size_t)node * 64 + c) = acc;
}

// ---------------- readout ----------------
__global__ void final_kernel(const float* __restrict__ linW,
                             const float* __restrict__ linb,
                             float* __restrict__ out)
{
    __shared__ float ps[(NLAYERS + 1) * 64];
    int g = blockIdx.x, t = threadIdx.x;
    for (int i = t; i < (NLAYERS + 1) * 64; i += 64) {
        int l = i >> 6, j = i & 63;
        ps[i] = g_pooled[(size_t)l * GG * 64 + (size_t)g * 64 + j];
    }
    __syncthreads();
    float acc = (float)g_cnt[g] * linb[t];
#pragma unroll
    for (int l = 1; l < NLAYERS + 1; l++) acc += linb[l * 64 + t];
    for (int l = 0; l < NLAYERS + 1; l++) {
        const float* wl = linW + (size_t)l * 64 * 64;
#pragma unroll 8
        for (int j = 0; j < 64; j++)
            acc += ps[l * 64 + j] * wl[j * 64 + t];
    }
    out[(size_t)g * 64 + t] = acc;
}

// ---------------- launch ----------------

extern "C" void kernel_launch(void* const* d_in, const int* in_sizes, int n_in,
                              void* d_out, int out_size)
{
    const float* x     = (const float*)d_in[0];
    const int*   edge  = (const int*)d_in[1];
    const int*   batch = (const int*)d_in[2];
    const float* fW1 = (const float*)d_in[3];
    const float* fb1 = (const float*)d_in[4];
    const float* fg1 = (const float*)d_in[5];
    const float* fbt1= (const float*)d_in[6];
    const float* fW2 = (const float*)d_in[7];
    const float* fb2 = (const float*)d_in[8];
    const float* fg2 = (const float*)d_in[9];
    const float* fbt2= (const float*)d_in[10];
    const float* cW1 = (const float*)d_in[11];
    const float* cb1 = (const float*)d_in[12];
    const float* cg1 = (const float*)d_in[13];
    const float* cbt1= (const float*)d_in[14];
    const float* cW2 = (const float*)d_in[15];
    const float* cb2 = (const float*)d_in[16];
    const float* cg2 = (const float*)d_in[17];
    const float* cbt2= (const float*)d_in[18];
    const float* linW= (const float*)d_in[19];
    const float* linb= (const float*)d_in[20];

    const int gemm_blocks = (NN + 63) / 64;        // 1563
    const int epi_blocks  = (NN + 15) / 16;        // 6250
    const int gat_blocks  = (NN * 16) / 256;       // 6250 (exact)

    zero_kernel<<<640, 256>>>();
    count_kernel<<<(EE + 255) / 256, 256>>>(edge, batch);
    scan_block_kernel<<<SCAN_NBLK, 1024>>>();
    scan_top_kernel<<<1, 128>>>();
    scan_add_kernel<<<SCAN_NBLK, 1024>>>();
    fill_csr_kernel<<<(EE + 255) / 256, 256>>>(edge);

    // first_h
    gemm_bn_kernel<<<gemm_blocks, 256>>>(x, 0, FEADIM, fW1, fb1, -1, 0, 0, fg1, fbt1);
    gemm_bn_kernel<<<gemm_blocks, 256>>>(nullptr, 1, HH, fW2, fb2, 0, 1, 1, fg2, fbt2);
    epilogue_kernel<<<epi_blocks, 256>>>(1, 0, batch);

    for (int l = 0; l < NLAYERS; l++) {
        int sA = 2 + 2 * l, sB = 3 + 2 * l;
        gather_kernel<<<gat_blocks, 256>>>();
        gemm_bn_kernel<<<gemm_blocks, 256>>>(nullptr, 2, HH,
                                             cW1 + (size_t)l * HH * HH, cb1 + l * HH,
                                             -1, 0, sA, cg1 + l * HH, cbt1 + l * HH);
        gemm_bn_kernel<<<gemm_blocks, 256>>>(nullptr, 1, HH,
                                             cW2 + (size_t)l * HH * HH, cb2 + l * HH,
                                             sA, 1, sB, cg2 + l * HH, cbt2 + l * HH);
        epilogue_kernel<<<epi_blocks, 256>>>(sB, l + 1, batch);
    }

    final_kernel<<<GG, 64>>>(linW, linb, (float*)d_out);
}

// round 5
// speedup vs baseline: 1.5652x; 1.2447x over previous
#include <cuda_runtime.h>
#include <cstdint>

#define NN 100000
#define EE 1600000
#define FEADIM 128
#define HH 64
#define GG 512
#define NLAYERS 4
#define BN_EPS 1e-5f
#define SCAN_NBLK 98   // ceil((NN+1)/1024)
#define GEMM_BLOCKS ((NN + 127) / 128)   // 782

// ---------------- scratch (static device globals; no allocation) ----------------
__device__ float g_tA[(size_t)NN * HH];
__device__ float g_tB[(size_t)NN * HH];
__device__ float g_z[(size_t)NN * HH];
__device__ float g_stats[10 * 128];            // per-stage [sum(64), sumsq(64)]
__device__ float g_ab[10 * 128];               // per-stage [a(64), c(64)] folded BN affine
__device__ float g_pooled[(NLAYERS + 1) * GG * HH];
__device__ int   g_cnt[GG];
__device__ int   g_deg[NN];
__device__ int   g_cur[NN];
__device__ int   g_off[NN + 1];
__device__ int   g_bsum[SCAN_NBLK];
__device__ int   g_bsum2[SCAN_NBLK];
__device__ int   g_csr[EE];
__device__ int   g_done[16];

__device__ __forceinline__ void red_add_v4(float* p, float4 v) {
    asm volatile("red.global.add.v4.f32 [%0], {%1,%2,%3,%4};"
                 :: "l"(p), "f"(v.x), "f"(v.y), "f"(v.z), "f"(v.w) : "memory");
}

__device__ __forceinline__ uint32_t f2tf32(float f) {
    uint32_t r;
    asm("cvt.rna.tf32.f32 %0, %1;" : "=r"(r) : "f"(f));
    return r;
}

__device__ __forceinline__ void mma_tf32(float& c0, float& c1, float& c2, float& c3,
                                         uint32_t a0, uint32_t a1, uint32_t a2, uint32_t a3,
                                         uint32_t b0, uint32_t b1) {
    asm volatile("mma.sync.aligned.m16n8k8.row.col.f32.tf32.tf32.f32 "
                 "{%0,%1,%2,%3}, {%4,%5,%6,%7}, {%8,%9}, {%0,%1,%2,%3};"
                 : "+f"(c0), "+f"(c1), "+f"(c2), "+f"(c3)
                 : "r"(a0), "r"(a1), "r"(a2), "r"(a3), "r"(b0), "r"(b1));
}

// ---------------- setup kernels ----------------

__global__ void zero_kernel() {
    const int TOT = (NLAYERS + 1) * GG * HH;   // 163840, largest
    for (int i = blockIdx.x * blockDim.x + threadIdx.x; i < TOT;
         i += gridDim.x * blockDim.x) {
        g_pooled[i] = 0.f;
        if (i < NN) { g_deg[i] = 0; g_cur[i] = 0; }
        if (i < 10 * 128) g_stats[i] = 0.f;
        if (i < GG) g_cnt[i] = 0;
        if (i < 16) g_done[i] = 0;
    }
}

__global__ void count_kernel(const int* __restrict__ edge, const int* __restrict__ batch) {
    int i = blockIdx.x * blockDim.x + threadIdx.x;
    if (i < EE) atomicAdd(&g_deg[edge[EE + i]], 1);
    if (i < NN) atomicAdd(&g_cnt[batch[i]], 1);
}

__global__ void scan_block_kernel() {
    __shared__ int s[1024];
    int tid = threadIdx.x;
    int i = blockIdx.x * 1024 + tid;
    int v = (i < NN) ? g_deg[i] : 0;
    s[tid] = v;
    __syncthreads();
    for (int off = 1; off < 1024; off <<= 1) {
        int t = (tid >= off) ? s[tid - off] : 0;
        __syncthreads();
        s[tid] += t;
        __syncthreads();
    }
    if (i <= NN) g_off[i] = s[tid] - v;
    if (tid == 1023) g_bsum[blockIdx.x] = s[1023];
}

__global__ void scan_top_kernel() {
    __shared__ int s[128];
    int tid = threadIdx.x;
    int v = (tid < SCAN_NBLK) ? g_bsum[tid] : 0;
    s[tid] = v;
    __syncthreads();
    for (int off = 1; off < 128; off <<= 1) {
        int t = (tid >= off) ? s[tid - off] : 0;
        __syncthreads();
        s[tid] += t;
        __syncthreads();
    }
    if (tid < SCAN_NBLK) g_bsum2[tid] = s[tid] - v;
}

__global__ void scan_add_kernel() {
    int i = blockIdx.x * 1024 + threadIdx.x;
    if (i <= NN) g_off[i] += g_bsum2[i >> 10];
}

__global__ void fill_csr_kernel(const int* __restrict__ edge) {
    int e = blockIdx.x * blockDim.x + threadIdx.x;
    if (e >= EE) return;
    int d = edge[EE + e];
    int pos = g_off[d] + atomicAdd(&g_cur[d], 1);
    g_csr[pos] = edge[e];
}

// ---------------- tf32 tensor-core GEMM + fused BN stats & finalize ----------------
// Y[N,64] = f(A)[N,K] @ W[K,64] + bias;  f = optional relu(a*x+c) from g_ab[tstage].
// Block: 128 rows x 64 cols. 8 warps, each 16 rows. K chunked by 32.
// Last block to finish computes the folded BN affine for this stage.
__global__ __launch_bounds__(256) void gemm_tc_kernel(
    const float* __restrict__ Aext, int Asel, int K,
    const float* __restrict__ W, const float* __restrict__ bias,
    int tstage, int Ysel, int sstage,
    const float* __restrict__ gamma, const float* __restrict__ beta)
{
    const float* A = (Asel == 0) ? Aext : (Asel == 1 ? g_tA : g_z);
    float* Y = (Ysel == 0) ? g_tA : g_tB;
    const float* trans = (tstage >= 0) ? (g_ab + tstage * 128) : nullptr;
    float* stats = g_stats + sstage * 128;

    __shared__ uint32_t As_u[128 * 36];   // 128 rows x 32 k, pad 36 -> bank 4r+c
    __shared__ uint32_t Bs_u[32 * 72];    // 32 k x 64 n, pad 72 -> bank 8k+n
    __shared__ float    sw[8 * 128];      // per-warp [sum(64), sumsq(64)]
    __shared__ float    sstats[128];
    __shared__ bool     slast;

    int tid = threadIdx.x;
    int wid = tid >> 5;
    int lane = tid & 31;
    int g = lane >> 2, tig = lane & 3;
    int row0 = blockIdx.x * 128;
    int wr0 = wid * 16;

    if (tid < 128) sstats[tid] = 0.f;

    float c[8][4];
#pragma unroll
    for (int j = 0; j < 8; j++)
#pragma unroll
        for (int q = 0; q < 4; q++) c[j][q] = 0.f;

    const int nchunk = K >> 5;
    for (int ch = 0; ch < nchunk; ch++) {
        int k0 = ch * 32;
        // load A chunk: 128 rows x 32 k (1024 float4, 4 per thread)
#pragma unroll
        for (int i = 0; i < 4; i++) {
            int li = tid + i * 256;
            int r = li >> 3, c4 = li & 7;
            int grow = row0 + r;
            float4 v = make_float4(0.f, 0.f, 0.f, 0.f);
            if (grow < NN) v = *(const float4*)(A + (size_t)grow * K + k0 + c4 * 4);
            if (trans) {
                int kb = k0 + c4 * 4;
                v.x = fmaxf(0.f, trans[kb + 0] * v.x + trans[64 + kb + 0]);
                v.y = fmaxf(0.f, trans[kb + 1] * v.y + trans[64 + kb + 1]);
                v.z = fmaxf(0.f, trans[kb + 2] * v.z + trans[64 + kb + 2]);
                v.w = fmaxf(0.f, trans[kb + 3] * v.w + trans[64 + kb + 3]);
            }
            uint4 u;
            u.x = f2tf32(v.x); u.y = f2tf32(v.y); u.z = f2tf32(v.z); u.w = f2tf32(v.w);
            *(uint4*)(&As_u[r * 36 + c4 * 4]) = u;
        }
        // load W chunk: 32 k x 64 n (512 float4, 2 per thread)
#pragma unroll
        for (int i = 0; i < 2; i++) {
            int li = tid + i * 256;
            int kr = li >> 4, n4 = li & 15;
            float4 w = *(const float4*)(W + (size_t)(k0 + kr) * 64 + n4 * 4);
            uint4 u;
            u.x = f2tf32(w.x); u.y = f2tf32(w.y); u.z = f2tf32(w.z); u.w = f2tf32(w.w);
            *(uint4*)(&Bs_u[kr * 72 + n4 * 4]) = u;
        }
        __syncthreads();

#pragma unroll
        for (int s = 0; s < 4; s++) {
            int k8 = s * 8;
            uint32_t a0 = As_u[(wr0 + g) * 36 + k8 + tig];
            uint32_t a1 = As_u[(wr0 + g + 8) * 36 + k8 + tig];
            uint32_t a2 = As_u[(wr0 + g) * 36 + k8 + tig + 4];
            uint32_t a3 = As_u[(wr0 + g + 8) * 36 + k8 + tig + 4];
#pragma unroll
            for (int j = 0; j < 8; j++) {
                uint32_t b0 = Bs_u[(k8 + tig) * 72 + j * 8 + g];
                uint32_t b1 = Bs_u[(k8 + tig + 4) * 72 + j * 8 + g];
                mma_tf32(c[j][0], c[j][1], c[j][2], c[j][3], a0, a1, a2, a3, b0, b1);
            }
        }
        __syncthreads();
    }

    // epilogue: bias, store, per-column stats (valid rows only)
    int rlo = row0 + wr0 + g;
    int rhi = rlo + 8;
    bool vlo = rlo < NN, vhi = rhi < NN;
#pragma unroll
    for (int j = 0; j < 8; j++) {
        int e0 = j * 8 + 2 * tig;
        float b0 = bias[e0], b1 = bias[e0 + 1];
        float y00 = c[j][0] + b0, y01 = c[j][1] + b1;   // row rlo
        float y10 = c[j][2] + b0, y11 = c[j][3] + b1;   // row rhi
        if (vlo) *(float2*)(Y + (size_t)rlo * 64 + e0) = make_float2(y00, y01);
        if (vhi) *(float2*)(Y + (size_t)rhi * 64 + e0) = make_float2(y10, y11);
        float s0 = (vlo ? y00 : 0.f) + (vhi ? y10 : 0.f);
        float s1 = (vlo ? y01 : 0.f) + (vhi ? y11 : 0.f);
        float q0 = (vlo ? y00 * y00 : 0.f) + (vhi ? y10 * y10 : 0.f);
        float q1 = (vlo ? y01 * y01 : 0.f) + (vhi ? y11 * y11 : 0.f);
        // reduce over the 8 row-groups (lanes differing in bits 2..4)
#pragma unroll
        for (int m = 4; m <= 16; m <<= 1) {
            s0 += __shfl_xor_sync(0xffffffffu, s0, m);
            s1 += __shfl_xor_sync(0xffffffffu, s1, m);
            q0 += __shfl_xor_sync(0xffffffffu, q0, m);
            q1 += __shfl_xor_sync(0xffffffffu, q1, m);
        }
        if (g == 0) {
            sw[wid * 128 + e0] = s0;
            sw[wid * 128 + e0 + 1] = s1;
            sw[wid * 128 + 64 + e0] = q0;
            sw[wid * 128 + 64 + e0 + 1] = q1;
        }
    }
    __syncthreads();
    if (tid < 128) {
        float tot = 0.f;
#pragma unroll
        for (int w = 0; w < 8; w++) tot += sw[w * 128 + tid];
        atomicAdd(&stats[tid], tot);
        __threadfence();
    }
    __syncthreads();
    if (tid == 0) {
        int v = atomicAdd(&g_done[sstage], 1);
        slast = (v == (int)gridDim.x - 1);
    }
    __syncthreads();
    if (slast && tid < 64) {
        float s_ = __ldcg(&stats[tid]);
        float q_ = __ldcg(&stats[64 + tid]);
        float m = s_ * (1.f / NN);
        float var = q_ * (1.f / NN) - m * m;
        float a = gamma[tid] * rsqrtf(var + BN_EPS);
        g_ab[sstage * 128 + tid] = a;
        g_ab[sstage * 128 + 64 + tid] = beta[tid] - a * m;
    }
}

// ---------------- epilogue: pooling of relu(a*tB+c) (h never materialized) ----------------
__global__ __launch_bounds__(256) void epilogue_kernel(int sstage, int level,
                                                       const int* __restrict__ batch)
{
    __shared__ float4 su[16][17];
    __shared__ int sb[16];
    const float* T = g_tB;
    const float* ab = g_ab + sstage * 128;
    float* pooled_level = g_pooled + (size_t)level * GG * HH;
    int tid = threadIdx.x;
    int rl = tid >> 4, qq = tid & 15;
    int r = blockIdx.x * 16 + rl;
    int cc = qq * 4;
    float4 u = make_float4(0.f, 0.f, 0.f, 0.f);
    int b = -1;
    if (r < NN) {
        float4 v = *(const float4*)(T + (size_t)r * 64 + cc);
        u.x = fmaxf(0.f, ab[cc + 0] * v.x + ab[64 + cc + 0]);
        u.y = fmaxf(0.f, ab[cc + 1] * v.y + ab[64 + cc + 1]);
        u.z = fmaxf(0.f, ab[cc + 2] * v.z + ab[64 + cc + 2]);
        u.w = fmaxf(0.f, ab[cc + 3] * v.w + ab[64 + cc + 3]);
        b = batch[r];
    }
    if (qq == 0) sb[rl] = b;
    su[rl][qq] = u;
    __syncthreads();
    if (r < NN) {
        bool head = (rl == 0) || (b != sb[rl - 1]);
        if (head) {
            float4 acc = u;
            for (int k = rl + 1; k < 16 && sb[k] == b; k++) {
                float4 w = su[k][qq];
                acc.x += w.x; acc.y += w.y; acc.z += w.z; acc.w += w.w;
            }
            red_add_v4(pooled_level + (size_t)b * 64 + cc, acc);
        }
    }
}

// ---------------- CSR gather with on-the-fly activation ----------------
// z[i] = relu(ab∘tB[i]) + sum_{j->i} relu(ab∘tB[j])
__global__ __launch_bounds__(256) void gather_kernel(int tstage) {
    int gt = blockIdx.x * 256 + threadIdx.x;
    int node = gt >> 4;              // grid sized so node < NN always
    int lane16 = threadIdx.x & 15;
    int cc = lane16 * 4;
    const float* ab = g_ab + tstage * 128;
    float a0 = ab[cc + 0], a1 = ab[cc + 1], a2 = ab[cc + 2], a3 = ab[cc + 3];
    float o0 = ab[64 + cc + 0], o1 = ab[64 + cc + 1], o2 = ab[64 + cc + 2], o3 = ab[64 + cc + 3];

    int off0 = g_off[node];
    int cnt = g_off[node + 1] - off0;

    float4 t = *(const float4*)(g_tB + (size_t)node * 64 + cc);
    float4 acc;
    acc.x = fmaxf(0.f, a0 * t.x + o0);
    acc.y = fmaxf(0.f, a1 * t.y + o1);
    acc.z = fmaxf(0.f, a2 * t.z + o2);
    acc.w = fmaxf(0.f, a3 * t.w + o3);

    int vmax = cnt;
#pragma unroll
    for (int sft = 16; sft > 0; sft >>= 1)
        vmax = max(vmax, __shfl_xor_sync(0xffffffffu, vmax, sft));

    for (int base = 0; base < vmax; base += 16) {
        int myidx = (base + lane16 < cnt) ? g_csr[off0 + base + lane16] : -1;
#pragma unroll
        for (int j = 0; j < 16; j++) {
            int idx = __shfl_sync(0xffffffffu, myidx, j, 16);
            if (idx >= 0) {
                float4 v = *(const float4*)(g_tB + (size_t)idx * 64 + cc);
                acc.x += fmaxf(0.f, a0 * v.x + o0);
                acc.y += fmaxf(0.f, a1 * v.y + o1);
                acc.z += fmaxf(0.f, a2 * v.z + o2);
                acc.w += fmaxf(0.f, a3 * v.w + o3);
            }
        }
    }
    *(float4*)(g_z + (size_t)node * 64 + cc) = acc;
}

// ---------------- readout ----------------
__global__ void final_kernel(const float* __restrict__ linW,
                             const float* __restrict__ linb,
                             float* __restrict__ out)
{
    __shared__ float ps[(NLAYERS + 1) * 64];
    int g = blockIdx.x, t = threadIdx.x;
    for (int i = t; i < (NLAYERS + 1) * 64; i += 64) {
        int l = i >> 6, j = i & 63;
        ps[i] = g_pooled[(size_t)l * GG * 64 + (size_t)g * 64 + j];
    }
    __syncthreads();
    float acc = (float)g_cnt[g] * linb[t];
#pragma unroll
    for (int l = 1; l < NLAYERS + 1; l++) acc += linb[l * 64 + t];
    for (int l = 0; l < NLAYERS + 1; l++) {
        const float* wl = linW + (size_t)l * 64 * 64;
#pragma unroll 8
        for (int j = 0; j < 64; j++)
            acc += ps[l * 64 + j] * wl[j * 64 + t];
    }
    out[(size_t)g * 64 + t] = acc;
}

// ---------------- launch ----------------

extern "C" void kernel_launch(void* const* d_in, const int* in_sizes, int n_in,
                              void* d_out, int out_size)
{
    const float* x     = (const float*)d_in[0];
    const int*   edge  = (const int*)d_in[1];
    const int*   batch = (const int*)d_in[2];
    const float* fW1 = (const float*)d_in[3];
    const float* fb1 = (const float*)d_in[4];
    const float* fg1 = (const float*)d_in[5];
    const float* fbt1= (const float*)d_in[6];
    const float* fW2 = (const float*)d_in[7];
    const float* fb2 = (const float*)d_in[8];
    const float* fg2 = (const float*)d_in[9];
    const float* fbt2= (const float*)d_in[10];
    const float* cW1 = (const float*)d_in[11];
    const float* cb1 = (const float*)d_in[12];
    const float* cg1 = (const float*)d_in[13];
    const float* cbt1= (const float*)d_in[14];
    const float* cW2 = (const float*)d_in[15];
    const float* cb2 = (const float*)d_in[16];
    const float* cg2 = (const float*)d_in[17];
    const float* cbt2= (const float*)d_in[18];
    const float* linW= (const float*)d_in[19];
    const float* linb= (const float*)d_in[20];

    const int epi_blocks = (NN + 15) / 16;        // 6250
    const int gat_blocks = (NN * 16) / 256;       // 6250 (exact)

    zero_kernel<<<640, 256>>>();
    count_kernel<<<(EE + 255) / 256, 256>>>(edge, batch);
    scan_block_kernel<<<SCAN_NBLK, 1024>>>();
    scan_top_kernel<<<1, 128>>>();
    scan_add_kernel<<<SCAN_NBLK, 1024>>>();
    fill_csr_kernel<<<(EE + 255) / 256, 256>>>(edge);

    // first_h
    gemm_tc_kernel<<<GEMM_BLOCKS, 256>>>(x, 0, FEADIM, fW1, fb1, -1, 0, 0, fg1, fbt1);
    gemm_tc_kernel<<<GEMM_BLOCKS, 256>>>(nullptr, 1, HH, fW2, fb2, 0, 1, 1, fg2, fbt2);
    epilogue_kernel<<<epi_blocks, 256>>>(1, 0, batch);

    for (int l = 0; l < NLAYERS; l++) {
        int sA = 2 + 2 * l, sB = 3 + 2 * l;
        gather_kernel<<<gat_blocks, 256>>>(2 * l + 1);
        gemm_tc_kernel<<<GEMM_BLOCKS, 256>>>(nullptr, 2, HH,
                                             cW1 + (size_t)l * HH * HH, cb1 + l * HH,
                                             -1, 0, sA, cg1 + l * HH, cbt1 + l * HH);
        gemm_tc_kernel<<<GEMM_BLOCKS, 256>>>(nullptr, 1, HH,
                                             cW2 + (size_t)l * HH * HH, cb2 + l * HH,
                                             sA, 1, sB, cg2 + l * HH, cbt2 + l * HH);
        epilogue_kernel<<<epi_blocks, 256>>>(sB, l + 1, batch);
    }

    final_kernel<<<GG, 64>>>(linW, linb, (float*)d_out);
}